// round 6
// baseline (speedup 1.0000x reference)
#include <cuda_runtime.h>
#include <cuda_fp16.h>
#include <mma.h>
#include <math_constants.h>

using namespace nvcuda;

// ---------------- scratch (device globals; no allocation allowed) ----------
#define NMAX 131072
#define EMAX 2097152   // >= E + 3*N padding
#define SENT (NMAX - 1)

__device__ __align__(16) __half2 g_u1h[NMAX * 32];   // u1 fp16, 32 half2/node
__device__ __align__(16) float   g_v1[NMAX * 64];
__device__ __align__(16) __half  g_h1h[NMAX * 64];   // h1 fp16
__device__ __align__(16) __half2 g_u2h[NMAX * 64];   // u2 fp16, 64 half2/node
__device__ __align__(16) float   g_v2[NMAX * 128];
__device__ int g_cnt[NMAX];          // zero at load; re-zeroed in k_alloc
__device__ int g_off[NMAX];
__device__ int g_end[NMAX];          // padded end (off + ceil(cnt/4)*4)
__device__ int g_cur[NMAX];
__device__ int g_cursor;             // reset in k_prep
__device__ __align__(16) int g_srcs[EMAX];

// ---------------- prep: u1/v1 per node (fp16 u1) + dst histogram ------------
__global__ void k_prep(const float* __restrict__ x, const float* __restrict__ W1,
                       const float* __restrict__ b1, const int* __restrict__ dst,
                       int n, int e) {
    int i = blockIdx.x * blockDim.x + threadIdx.x;
    if (i == 0) g_cursor = 0;
    int t1 = n * 32;
    if (i < t1) {
        int node = i >> 5, p = i & 5 * 0 + 31;   // p = i & 31
        float x0 = x[node * 3 + 0], x1 = x[node * 3 + 1], x2 = x[node * 3 + 2];
        float u[2], v[2];
#pragma unroll
        for (int k = 0; k < 2; k++) {
            int c = p * 2 + k;
            float wa0 = W1[0 * 64 + c], wa1 = W1[1 * 64 + c], wa2 = W1[2 * 64 + c];
            float wb0 = W1[3 * 64 + c], wb1 = W1[4 * 64 + c], wb2 = W1[5 * 64 + c];
            v[k] = x0 * wb0 + x1 * wb1 + x2 * wb2;
            u[k] = x0 * (wa0 + wb0) + x1 * (wa1 + wb1) + x2 * (wa2 + wb2) + b1[c];
        }
        g_u1h[i] = __floats2half2_rn(u[0], u[1]);
        *(float2*)&g_v1[node * 64 + p * 2] = make_float2(v[0], v[1]);
    } else {
        int j = i - t1;
        if (j < e) atomicAdd(&g_cnt[dst[j]], 1);
    }
}

// ---------------- alloc: block-aggregated cursor + sentinel pads ------------
__global__ void k_alloc(int n) {
    int tid = threadIdx.x;
    int i = blockIdx.x * 256 + tid;
    int lane = tid & 31, wid = tid >> 5;

    // sentinel node rows = -inf (fp16) so pad slots never win the max
    if (blockIdx.x == 0) {
        if (tid < 32) ((unsigned*)g_u1h)[SENT * 32 + tid] = 0xFC00FC00u;
        if (tid < 64) ((unsigned*)g_u2h)[SENT * 64 + tid] = 0xFC00FC00u;
    }

    int c = 0;
    if (i < n) { c = g_cnt[i]; g_cnt[i] = 0; }
    int len = (c + 3) & ~3;

    // inclusive warp scan of len
    int v = len;
#pragma unroll
    for (int o = 1; o < 32; o <<= 1) {
        int t = __shfl_up_sync(0xFFFFFFFFu, v, o);
        if (lane >= o) v += t;
    }
    __shared__ int wsum[8];
    __shared__ int sbase;
    if (lane == 31) wsum[wid] = v;
    __syncthreads();
    if (tid == 0) {
        int tot = 0;
#pragma unroll
        for (int w = 0; w < 8; w++) { int s = wsum[w]; wsum[w] = tot; tot += s; }
        sbase = atomicAdd(&g_cursor, tot);
    }
    __syncthreads();

    if (i < n) {
        int o = sbase + wsum[wid] + (v - len);   // exclusive prefix
        g_off[i] = o;
        g_end[i] = o + len;
        g_cur[i] = o;
        for (int p = o + c; p < o + len; p++) g_srcs[p] = SENT;
    }
}

__global__ void k_scatter(const int* __restrict__ src, const int* __restrict__ dst,
                          int e) {
    int i = blockIdx.x * blockDim.x + threadIdx.x;
    if (i >= e) return;
    int d = dst[i];
    int p = atomicAdd(&g_cur[d], 1);
    g_srcs[p] = src[i];
}

// ---------------- aggregation ------------------------------------------------

// layer-1 gather-max + relu -> h1 (fp16). One warp/node.
// src indices fetched once coalesced, broadcast by shfl.
__global__ void k_agg1(int n) {
    int gt = blockIdx.x * blockDim.x + threadIdx.x;
    int node = gt >> 5, lane = gt & 31;
    if (node >= n) return;
    int off = g_off[node];
    int len = g_end[node] - off;
    __half2 m = __halves2half2(__ushort_as_half(0xFC00), __ushort_as_half(0xFC00));
    if (len > 0) {
        int sidx = g_srcs[off + min(lane, len - 1)];
        int nf = min(len, 32);
        for (int j = 0; j < nf; j += 4) {
            int s0 = __shfl_sync(0xFFFFFFFFu, sidx, j);
            int s1 = __shfl_sync(0xFFFFFFFFu, sidx, j + 1);
            int s2 = __shfl_sync(0xFFFFFFFFu, sidx, j + 2);
            int s3 = __shfl_sync(0xFFFFFFFFu, sidx, j + 3);
            __half2 a = g_u1h[s0 * 32 + lane];
            __half2 b = g_u1h[s1 * 32 + lane];
            __half2 c = g_u1h[s2 * 32 + lane];
            __half2 d = g_u1h[s3 * 32 + lane];
            m = __hmax2(m, __hmax2(__hmax2(a, b), __hmax2(c, d)));
        }
        for (int j = 32; j < len; j += 4) {          // rare (deg > 32)
            int4 s = *(const int4*)&g_srcs[off + j];
            __half2 a = g_u1h[s.x * 32 + lane];
            __half2 b = g_u1h[s.y * 32 + lane];
            __half2 c = g_u1h[s.z * 32 + lane];
            __half2 d = g_u1h[s.w * 32 + lane];
            m = __hmax2(m, __hmax2(__hmax2(a, b), __hmax2(c, d)));
        }
    }
    float2 mf = __half22float2(m);
    float2 v = *(const float2*)&g_v1[node * 64 + lane * 2];
    float h0 = fmaxf(mf.x - v.x, 0.0f);
    float h1 = fmaxf(mf.y - v.y, 0.0f);
    *(__half2*)&g_h1h[node * 64 + lane * 2] = __floats2half2_rn(h0, h1);
}

// layer 2: U2 = H1 @ W2[0:64] + b2 + V2 ; V2 = x @ W2[64:67]
// Tensor-core GEMM: block = 64 nodes x 128 cols, 8 warps (4M x 2N), wmma 16x16x16.
__global__ void __launch_bounds__(256) k_u2v2(
        const float* __restrict__ x, const float* __restrict__ W2,
        const float* __restrict__ b2, int n) {
    __shared__ __align__(16) unsigned char sraw[32768];   // W2h+H  /  Acc
    __shared__ float sWx[3][128];
    __shared__ float sx[64][3];
    __half* sW2h = (__half*)sraw;            // [64][128] halves, 16 KB
    __half* sH   = (__half*)(sraw + 16384);  // [64][64]  halves,  8 KB
    float*  sAcc = (float*)sraw;             // [64][128] floats, 32 KB (epilogue)

    int node0 = blockIdx.x * 64;
    int t = threadIdx.x;
    int wid = t >> 5;

    for (int i = t * 4; i < 8192; i += 1024) {
        float4 w = *(const float4*)&W2[i];
        ((__half2*)sW2h)[i / 2]     = __floats2half2_rn(w.x, w.y);
        ((__half2*)sW2h)[i / 2 + 1] = __floats2half2_rn(w.z, w.w);
    }
    if (t < 96) {
        int i = t * 4;
        *(float4*)&sWx[i >> 7][i & 127] = *(const float4*)&W2[64 * 128 + i];
    }
    for (int i = t; i < 512; i += 256) {
        int r = i >> 3, q = i & 7;
        int node = node0 + r;
        uint4 v = make_uint4(0u, 0u, 0u, 0u);
        if (node < n) v = *(const uint4*)&g_h1h[node * 64 + q * 8];
        *(uint4*)&sH[r * 64 + q * 8] = v;
    }
    if (t < 192) {
        int r = t / 3, c = t % 3;
        int node = node0 + r;
        sx[r][c] = (node < n) ? x[node * 3 + c] : 0.f;
    }
    __syncthreads();

    int wm = wid & 3;
    int wn = wid >> 2;
    wmma::fragment<wmma::accumulator, 16, 16, 16, float> acc[4];
#pragma unroll
    for (int i = 0; i < 4; i++) wmma::fill_fragment(acc[i], 0.0f);
#pragma unroll
    for (int k = 0; k < 4; k++) {
        wmma::fragment<wmma::matrix_a, 16, 16, 16, __half, wmma::row_major> a;
        wmma::load_matrix_sync(a, sH + (wm * 16) * 64 + k * 16, 64);
#pragma unroll
        for (int nt = 0; nt < 4; nt++) {
            wmma::fragment<wmma::matrix_b, 16, 16, 16, __half, wmma::row_major> b;
            wmma::load_matrix_sync(b, sW2h + (k * 16) * 128 + wn * 64 + nt * 16, 128);
            wmma::mma_sync(acc[nt], a, b, acc[nt]);
        }
    }
    __syncthreads();
#pragma unroll
    for (int nt = 0; nt < 4; nt++)
        wmma::store_matrix_sync(sAcc + (wm * 16) * 128 + wn * 64 + nt * 16,
                                acc[nt], 128, wmma::mem_row_major);
    __syncthreads();

    for (int i = t * 4; i < 8192; i += 1024) {
        int r = i >> 7, c = i & 127;
        int node = node0 + r;
        if (node >= n) continue;
        float4 a4 = *(float4*)&sAcc[i];
        float x0 = sx[r][0], x1 = sx[r][1], x2 = sx[r][2];
        float4 vv;
        vv.x = x0 * sWx[0][c + 0] + x1 * sWx[1][c + 0] + x2 * sWx[2][c + 0];
        vv.y = x0 * sWx[0][c + 1] + x1 * sWx[1][c + 1] + x2 * sWx[2][c + 1];
        vv.z = x0 * sWx[0][c + 2] + x1 * sWx[1][c + 2] + x2 * sWx[2][c + 2];
        vv.w = x0 * sWx[0][c + 3] + x1 * sWx[1][c + 3] + x2 * sWx[2][c + 3];
        float4 bb = *(const float4*)&b2[c];
        __half2 u01 = __floats2half2_rn(a4.x + bb.x + vv.x, a4.y + bb.y + vv.y);
        __half2 u23 = __floats2half2_rn(a4.z + bb.z + vv.z, a4.w + bb.w + vv.w);
        uint2 upk;
        upk.x = *(unsigned*)&u01;
        upk.y = *(unsigned*)&u23;
        *(uint2*)&g_u2h[node * 64 + (c >> 1)] = upk;
        *(float4*)&g_v2[node * 128 + c] = vv;
    }
}

// layer-2 gather-max fused with output head: one warp/node, shfl src broadcast
__global__ void k_agg2out(const float* __restrict__ Wc, const float* __restrict__ bc,
                          float* __restrict__ out, int n) {
    int gt = blockIdx.x * blockDim.x + threadIdx.x;
    int node = gt >> 5, lane = gt & 31;
    if (node >= n) return;
    int off = g_off[node];
    int len = g_end[node] - off;
    __half2 m0 = __halves2half2(__ushort_as_half(0xFC00), __ushort_as_half(0xFC00));
    __half2 m1 = m0;
    if (len > 0) {
        int sidx = g_srcs[off + min(lane, len - 1)];
        int nf = min(len, 32);
        for (int j = 0; j < nf; j += 4) {
            int s0 = __shfl_sync(0xFFFFFFFFu, sidx, j);
            int s1 = __shfl_sync(0xFFFFFFFFu, sidx, j + 1);
            int s2 = __shfl_sync(0xFFFFFFFFu, sidx, j + 2);
            int s3 = __shfl_sync(0xFFFFFFFFu, sidx, j + 3);
            uint2 ra = *(const uint2*)&g_u2h[s0 * 64 + lane * 2];
            uint2 rb = *(const uint2*)&g_u2h[s1 * 64 + lane * 2];
            uint2 rc = *(const uint2*)&g_u2h[s2 * 64 + lane * 2];
            uint2 rd = *(const uint2*)&g_u2h[s3 * 64 + lane * 2];
            m0 = __hmax2(m0, __hmax2(__hmax2(*(__half2*)&ra.x, *(__half2*)&rb.x),
                                     __hmax2(*(__half2*)&rc.x, *(__half2*)&rd.x)));
            m1 = __hmax2(m1, __hmax2(__hmax2(*(__half2*)&ra.y, *(__half2*)&rb.y),
                                     __hmax2(*(__half2*)&rc.y, *(__half2*)&rd.y)));
        }
        for (int j = 32; j < len; j += 4) {          // rare (deg > 32)
            int4 s = *(const int4*)&g_srcs[off + j];
            uint2 ra = *(const uint2*)&g_u2h[s.x * 64 + lane * 2];
            uint2 rb = *(const uint2*)&g_u2h[s.y * 64 + lane * 2];
            uint2 rc = *(const uint2*)&g_u2h[s.z * 64 + lane * 2];
            uint2 rd = *(const uint2*)&g_u2h[s.w * 64 + lane * 2];
            m0 = __hmax2(m0, __hmax2(__hmax2(*(__half2*)&ra.x, *(__half2*)&rb.x),
                                     __hmax2(*(__half2*)&rc.x, *(__half2*)&rd.x)));
            m1 = __hmax2(m1, __hmax2(__hmax2(*(__half2*)&ra.y, *(__half2*)&rb.y),
                                     __hmax2(*(__half2*)&rc.y, *(__half2*)&rd.y)));
        }
    }
    float2 f0 = __half22float2(m0);
    float2 f1 = __half22float2(m1);
    float4 v = *(const float4*)&g_v2[node * 128 + lane * 4];
    float h0 = fmaxf(f0.x - v.x, 0.0f);
    float h1 = fmaxf(f0.y - v.y, 0.0f);
    float h2 = fmaxf(f1.x - v.z, 0.0f);
    float h3 = fmaxf(f1.y - v.w, 0.0f);

    int c = lane * 4;
    const float* w0 = Wc + (c + 0) * 5;
    const float* w1 = Wc + (c + 1) * 5;
    const float* w2 = Wc + (c + 2) * 5;
    const float* w3 = Wc + (c + 3) * 5;
    float a0 = h0 * w0[0] + h1 * w1[0] + h2 * w2[0] + h3 * w3[0];
    float a1 = h0 * w0[1] + h1 * w1[1] + h2 * w2[1] + h3 * w3[1];
    float a2 = h0 * w0[2] + h1 * w1[2] + h2 * w2[2] + h3 * w3[2];
    float a3 = h0 * w0[3] + h1 * w1[3] + h2 * w2[3] + h3 * w3[3];
    float a4 = h0 * w0[4] + h1 * w1[4] + h2 * w2[4] + h3 * w3[4];
#pragma unroll
    for (int o = 16; o; o >>= 1) {
        a0 += __shfl_xor_sync(0xFFFFFFFFu, a0, o);
        a1 += __shfl_xor_sync(0xFFFFFFFFu, a1, o);
        a2 += __shfl_xor_sync(0xFFFFFFFFu, a2, o);
        a3 += __shfl_xor_sync(0xFFFFFFFFu, a3, o);
        a4 += __shfl_xor_sync(0xFFFFFFFFu, a4, o);
    }
    if (lane == 0) {
        float l0 = a0 + bc[0], l1 = a1 + bc[1], l2 = a2 + bc[2];
        float l3 = a3 + bc[3], l4 = a4 + bc[4];
        float mm = fmaxf(fmaxf(fmaxf(l0, l1), fmaxf(l2, l3)), l4);
        float s = expf(l0 - mm) + expf(l1 - mm) + expf(l2 - mm) +
                  expf(l3 - mm) + expf(l4 - mm);
        float lse = mm + logf(s);
        float* o = out + node * 5;
        o[0] = l0 - lse; o[1] = l1 - lse; o[2] = l2 - lse;
        o[3] = l3 - lse; o[4] = l4 - lse;
    }
}

// ---------------- launch ------------------------------------------------------
extern "C" void kernel_launch(void* const* d_in, const int* in_sizes, int n_in,
                              void* d_out, int out_size) {
    const float* x  = (const float*)d_in[0];
    const int*   ei = (const int*)d_in[1];
    const float* W1 = (const float*)d_in[2];
    const float* b1 = (const float*)d_in[3];
    const float* W2 = (const float*)d_in[4];
    const float* b2 = (const float*)d_in[5];
    const float* Wc = (const float*)d_in[6];
    const float* bc = (const float*)d_in[7];
    float* out = (float*)d_out;

    int n = in_sizes[0] / 3;   // 100000
    int e = in_sizes[1] / 2;   // 1600000
    const int* src = ei;
    const int* dst = ei + e;

    const int T = 256;

    k_prep    <<<(n * 32 + e + T - 1) / T, T>>>(x, W1, b1, dst, n, e);
    k_alloc   <<<(n + T - 1) / T, T>>>(n);
    k_scatter <<<(e + T - 1) / T, T>>>(src, dst, e);
    k_agg1    <<<(n * 32 + T - 1) / T, T>>>(n);
    k_u2v2    <<<(n + 63) / 64, 256>>>(x, W2, b2, n);
    k_agg2out <<<(n * 32 + T - 1) / T, T>>>(Wc, bc, out, n);
}